// round 17
// baseline (speedup 1.0000x reference)
#include <cuda_runtime.h>

#define IN_DIM 768
#define OUT_DIM 768
#define BATCH 32
#define NUMF 8
#define NROWS 9                    // 8 sin + 1 silu terms per i

#define CHUNK 8                    // i's per block
#define NSPLIT 96
#define O_TILE 64
#define THREADS 256                // 8 warps = 4 m16-bands x 2 n-halves
#define KT (CHUNK * NROWS)         // 72 = 9 k8-steps exactly

// interleaved (hi,lo) u32 pairs; strides tuned for LDS.64 phase-exact banking
#define AST 152                    // u32 row stride; 152%32==24
#define BST 72                     // u32 row stride; 72%32==8
#define OFF_A 0
#define OFF_B (O_TILE * AST)                  // 9728
#define SMEM_U32 (OFF_B + KT * BST)           // 14912
#define SMEM_BYTES (SMEM_U32 * 4)             // 59648 B -> 3 blocks/SM

typedef unsigned int u32;
typedef unsigned long long u64;

__device__ __forceinline__ u32 to_tf32(float v) {
    u32 r; asm("cvt.rna.tf32.f32 %0, %1;" : "=r"(r) : "f"(v)); return r;
}
// store (hi, lo) as one u64: low word = hi (even slot), high word = lo
__device__ __forceinline__ void split_store64(u32* smbase, int slot, float v) {
    u32 hi = to_tf32(v);
    float lo = v - __uint_as_float(hi);
    u64 pair = (u64)hi | ((u64)__float_as_uint(lo) << 32);   // lo: HW truncates mantissa
    *reinterpret_cast<u64*>(smbase + slot) = pair;
}
__device__ __forceinline__ void mma_tf32(float c[4], const u32 a[4], u32 b0, u32 b1) {
    asm volatile(
        "mma.sync.aligned.m16n8k8.row.col.f32.tf32.tf32.f32 "
        "{%0,%1,%2,%3}, {%4,%5,%6,%7}, {%8,%9}, {%0,%1,%2,%3};"
        : "+f"(c[0]), "+f"(c[1]), "+f"(c[2]), "+f"(c[3])
        : "r"(a[0]), "r"(a[1]), "r"(a[2]), "r"(a[3]), "r"(b0), "r"(b1));
}
__device__ __forceinline__ void redg_f32(float* addr, float v) {
    asm volatile("red.global.add.f32 [%0], %1;" :: "l"(addr), "f"(v) : "memory");
}

// -------- fused kernel: basis + tf32-split staging + mma.sync GEMM + REDG --------
// Block = 64 o x 32 b x 8 i (K=72). Warp = (m16 band, n16 half).
__global__ __launch_bounds__(THREADS, 3) void mma_kernel(
    const float* __restrict__ x,
    const float* __restrict__ grid,
    const float* __restrict__ coef,
    const float* __restrict__ scale_sp,
    const float* __restrict__ scale_base,
    const float* __restrict__ bias_w,
    float* __restrict__ y) {

    extern __shared__ __align__(16) u32 sm[];
    int tid = threadIdx.x;
    int lane = tid & 31;
    int warp = tid >> 5;
    int split = blockIdx.y;
    int i0 = split * CHUNK;
    int oBase = blockIdx.x * O_TILE;

    // ---- B staging: basis, one (i, b) column per thread (256 = CHUNK*BATCH) ----
    {
        int ii = tid >> 5;
        int b = tid & 31;
        float xv = x[b * IN_DIM + i0 + ii];
        float theta = __ldg(grid) * xv;
        float vals[NROWS];
        vals[0] = __sinf(theta);
        float c2 = 2.0f * __cosf(theta);
        float sm1 = vals[0], sm2 = 0.0f;
#pragma unroll
        for (int k = 1; k < NUMF; k++) {
            float sk = fmaf(c2, sm1, -sm2);
            sm2 = sm1; sm1 = sk;
            vals[k] = sk;
        }
        vals[8] = xv / (1.0f + __expf(-xv));          // silu
#pragma unroll
        for (int r = 0; r < NROWS; r++)
            split_store64(sm + OFF_B, (ii * NROWS + r) * BST + 2 * b, vals[r]);
    }

    // ---- A staging: w = coef*scale_sp (r 0..7), scale_base (r 8); 2 granules/thread ----
#pragma unroll
    for (int g = 0; g < 2; g++) {
        int f = tid + g * THREADS;
        int o_l = f >> 3;                     // 0..63
        int i_l = f & 7;
        int idx = (oBase + o_l) * IN_DIM + i0 + i_l;
        float4 c0 = reinterpret_cast<const float4*>(coef)[idx * 2];
        float4 c1 = reinterpret_cast<const float4*>(coef)[idx * 2 + 1];
        float sp = __ldg(scale_sp + idx);
        float vals[NROWS];
        vals[0] = c0.x * sp; vals[1] = c0.y * sp; vals[2] = c0.z * sp; vals[3] = c0.w * sp;
        vals[4] = c1.x * sp; vals[5] = c1.y * sp; vals[6] = c1.z * sp; vals[7] = c1.w * sp;
        vals[8] = __ldg(scale_base + idx);
#pragma unroll
        for (int r = 0; r < NROWS; r++)
            split_store64(sm + OFF_A, o_l * AST + 2 * (i_l * NROWS + r), vals[r]);
    }
    __syncthreads();

    // ---- mainloop ----
    int mband = warp & 3;          // m16 band
    int nh = warp >> 2;            // n-half: tiles {2nh, 2nh+1}
    int gid = lane >> 2;           // 0..7
    int tq = lane & 3;             // 0..3
    int orow = mband * 16 + gid;

    float c[2][4], d[2][4];
#pragma unroll
    for (int t = 0; t < 2; t++)
#pragma unroll
        for (int q = 0; q < 4; q++) { c[t][q] = 0.0f; d[t][q] = 0.0f; }

#pragma unroll
    for (int ks = 0; ks < KT / 8; ks++) {      // 9 k-steps
        int k0 = ks * 8 + tq;
        u64 pa0 = *reinterpret_cast<const u64*>(sm + OFF_A + orow * AST + 2 * k0);
        u64 pa1 = *reinterpret_cast<const u64*>(sm + OFF_A + (orow + 8) * AST + 2 * k0);
        u64 pa2 = *reinterpret_cast<const u64*>(sm + OFF_A + orow * AST + 2 * (k0 + 4));
        u64 pa3 = *reinterpret_cast<const u64*>(sm + OFF_A + (orow + 8) * AST + 2 * (k0 + 4));
        u32 ahi[4] = {(u32)pa0, (u32)pa1, (u32)pa2, (u32)pa3};
        u32 alo[4] = {(u32)(pa0 >> 32), (u32)(pa1 >> 32),
                      (u32)(pa2 >> 32), (u32)(pa3 >> 32)};

#pragma unroll
        for (int t = 0; t < 2; t++) {
            int n = (2 * nh + t) * 8 + gid;
            u64 pb0 = *reinterpret_cast<const u64*>(sm + OFF_B + k0 * BST + 2 * n);
            u64 pb1 = *reinterpret_cast<const u64*>(sm + OFF_B + (k0 + 4) * BST + 2 * n);
            u32 bhi0 = (u32)pb0, blo0 = (u32)(pb0 >> 32);
            u32 bhi1 = (u32)pb1, blo1 = (u32)(pb1 >> 32);
            mma_tf32(c[t], ahi, bhi0, bhi1);     // hi*hi
            mma_tf32(d[t], ahi, blo0, blo1);     // hi*lo
            mma_tf32(d[t], alo, bhi0, bhi1);     // lo*hi
        }
    }

    // ---- epilogue: combine correction acc, REDG into y (+bias via split 0) ----
    {
        int o0 = oBase + mband * 16 + gid;
        int o8 = o0 + 8;
        float bw0 = (split == 0) ? __ldg(bias_w + o0) : 0.0f;
        float bw8 = (split == 0) ? __ldg(bias_w + o8) : 0.0f;
#pragma unroll
        for (int t = 0; t < 2; t++) {
            int bcol = (2 * nh + t) * 8 + 2 * tq;
            redg_f32(y + bcol * OUT_DIM + o0,       c[t][0] + d[t][0] + bw0);
            redg_f32(y + (bcol + 1) * OUT_DIM + o0, c[t][1] + d[t][1] + bw0);
            redg_f32(y + bcol * OUT_DIM + o8,       c[t][2] + d[t][2] + bw8);
            redg_f32(y + (bcol + 1) * OUT_DIM + o8, c[t][3] + d[t][3] + bw8);
        }
    }
}

extern "C" void kernel_launch(void* const* d_in, const int* in_sizes, int n_in,
                              void* d_out, int out_size) {
    // metadata order: x, grid, coef, bias_w, scale_base, scale_sp
    const float* x          = (const float*)d_in[0];
    const float* grid       = (const float*)d_in[1];
    const float* coef       = (const float*)d_in[2];
    const float* bias_w     = (const float*)d_in[3];
    const float* scale_base = (const float*)d_in[4];
    const float* scale_sp   = (const float*)d_in[5];
    float* y = (float*)d_out;

    cudaFuncSetAttribute(mma_kernel,
                         cudaFuncAttributeMaxDynamicSharedMemorySize, SMEM_BYTES);
    cudaMemsetAsync(y, 0, (size_t)out_size * sizeof(float));
    dim3 g(OUT_DIM / O_TILE, NSPLIT);        // 12 x 96 = 1152 blocks, 3/SM
    mma_kernel<<<g, THREADS, SMEM_BYTES>>>(x, grid, coef, scale_sp,
                                           scale_base, bias_w, y);
}